// round 1
// baseline (speedup 1.0000x reference)
#include <cuda_runtime.h>

// Problem constants
#define B_ 4
#define N_ 1024
#define H_ 256
#define D_ 32
#define M_ (B_ * N_)              // 4096 token rows
#define OUT_PER_B (D_ * D_ * H_)  // 262144

// Scratch (device globals — no allocation allowed)
__device__ float g_k0[M_ * D_];        // [b][n][d]
__device__ float g_v0[M_ * D_];        // [b][n][d]
__device__ float g_dk[M_ * D_];        // [b][n][d]
__device__ float g_khT[B_ * H_ * N_];  // [b][h][n]
__device__ float g_vhT[B_ * H_ * N_];  // [b][h][n]
__device__ float g_dhT[B_ * H_ * N_];  // [b][h][n]

__device__ __forceinline__ float sigmoidf_(float x) {
    return __fdividef(1.f, 1.f + __expf(-x));
}
__device__ __forceinline__ float siluf_(float x) {
    return __fdividef(x, 1.f + __expf(-x));
}

// ---------------------------------------------------------------------------
// Pass 1: projection GEMM. C = token(4096x256) @ [Wkv | Wkvh | Wd | Wdh]
// 864 total output columns; column-block of 32 always lies in one matrix
// (boundaries 64, 576, 608 are multiples of 32). Epilogue scatters into the
// scratch layouts pass 2 wants (d-indexed row-major; h-indexed transposed).
// ---------------------------------------------------------------------------
__global__ __launch_bounds__(256) void proj_kernel(
    const float* __restrict__ token,
    const float* __restrict__ Wkv,
    const float* __restrict__ Wkvh,
    const float* __restrict__ Wd,
    const float* __restrict__ Wdh)
{
    __shared__ __align__(16) float As[32][68];  // [k][m], padded
    __shared__ __align__(16) float Bs[32][34];  // [k][c], padded

    const int tid = threadIdx.x;
    const int m0 = blockIdx.y * 64;
    const int c0 = blockIdx.x * 32;

    const float* Wp; int width, coff;
    if (c0 < 64)       { Wp = Wkv;  width = 64;  coff = c0;       }
    else if (c0 < 576) { Wp = Wkvh; width = 512; coff = c0 - 64;  }
    else if (c0 < 608) { Wp = Wd;   width = 32;  coff = c0 - 576; }
    else               { Wp = Wdh;  width = 256; coff = c0 - 608; }

    const int tx = tid & 15;       // cols 2tx..2tx+1
    const int ty = tid >> 4;       // rows 4ty..4ty+3
    const int lr = tid >> 3;       // 0..31 (load row / k)
    const int lc = (tid & 7) * 4;  // 0,4,...,28 (load col group)

    float acc[4][2] = {};

    for (int kt = 0; kt < 256; kt += 32) {
        // A tile: 64 rows x 32 k, stored transposed As[k][m]
        #pragma unroll
        for (int rr = 0; rr < 64; rr += 32) {
            float4 a = *reinterpret_cast<const float4*>(
                &token[(size_t)(m0 + lr + rr) * 256 + kt + lc]);
            As[lc + 0][lr + rr] = a.x;
            As[lc + 1][lr + rr] = a.y;
            As[lc + 2][lr + rr] = a.z;
            As[lc + 3][lr + rr] = a.w;
        }
        // B tile: 32 k x 32 cols
        {
            float4 bv = *reinterpret_cast<const float4*>(
                &Wp[(size_t)(kt + lr) * width + coff + lc]);
            Bs[lr][lc + 0] = bv.x;
            Bs[lr][lc + 1] = bv.y;
            Bs[lr][lc + 2] = bv.z;
            Bs[lr][lc + 3] = bv.w;
        }
        __syncthreads();
        #pragma unroll
        for (int kk = 0; kk < 32; kk++) {
            float4 a = *reinterpret_cast<const float4*>(&As[kk][ty * 4]);
            float2 bb = *reinterpret_cast<const float2*>(&Bs[kk][tx * 2]);
            acc[0][0] = fmaf(a.x, bb.x, acc[0][0]);
            acc[0][1] = fmaf(a.x, bb.y, acc[0][1]);
            acc[1][0] = fmaf(a.y, bb.x, acc[1][0]);
            acc[1][1] = fmaf(a.y, bb.y, acc[1][1]);
            acc[2][0] = fmaf(a.z, bb.x, acc[2][0]);
            acc[2][1] = fmaf(a.z, bb.y, acc[2][1]);
            acc[3][0] = fmaf(a.w, bb.x, acc[3][0]);
            acc[3][1] = fmaf(a.w, bb.y, acc[3][1]);
        }
        __syncthreads();
    }

    #pragma unroll
    for (int i = 0; i < 4; i++) {
        int m = m0 + ty * 4 + i;
        int b = m >> 10, n = m & 1023;
        #pragma unroll
        for (int j = 0; j < 2; j++) {
            int cg = c0 + tx * 2 + j;
            float v = acc[i][j];
            if (cg < 32)       g_k0[m * 32 + cg] = v;
            else if (cg < 64)  g_v0[m * 32 + (cg - 32)] = v;
            else if (cg < 320) g_khT[((b << 8) + (cg - 64)) * 1024 + n] = v;
            else if (cg < 576) g_vhT[((b << 8) + (cg - 320)) * 1024 + n] = v;
            else if (cg < 608) g_dk[m * 32 + (cg - 576)] = v;
            else               g_dhT[((b << 8) + (cg - 608)) * 1024 + n] = v;
        }
    }
}

// ---------------------------------------------------------------------------
// Pass 2: per (b,h) pair — reversed-order sigmoid running-product weights,
// silu gating, and a 32x32x1024 rank-accumulation. One block per (b,h).
// Early-exits once all 32 per-d weight carries underflow to exact 0 (every
// remaining contribution is then exactly 0, matching the reference's fp32
// exp(-huge) = 0 behavior).
// ---------------------------------------------------------------------------
__global__ __launch_bounds__(256) void accum_kernel(float* __restrict__ out)
{
    __shared__ __align__(16) float sK[128][32];
    __shared__ __align__(16) float sV[128][32];
    __shared__ float sProd[8][32];
    __shared__ float sCarry[32];

    const int tid = threadIdx.x;
    const int bh = blockIdx.x;
    const int b = bh >> 8;
    const int h = bh & 255;

    const float* __restrict__ dk = g_dk + b * N_ * D_;
    const float* __restrict__ k0 = g_k0 + b * N_ * D_;
    const float* __restrict__ v0 = g_v0 + b * N_ * D_;
    const float* __restrict__ dh = g_dhT + (b * H_ + h) * N_;
    const float* __restrict__ kh = g_khT + (b * H_ + h) * N_;
    const float* __restrict__ vh = g_vhT + (b * H_ + h) * N_;

    if (tid < 32) sCarry[tid] = 1.f;

    // Phase A/B mapping: chunk c owns local n in [16c, 16c+16), lane d
    const int c = tid >> 5, d = tid & 31;
    // Phase C mapping: jq-quarter of the tile, 4x4 microtile (dg, eg)
    const int jq = tid >> 6;        // 0..3
    const int dg = (tid >> 3) & 7;  // d base = dg*4
    const int eg = tid & 7;         // e base = eg*4

    float acc[4][4] = {};

    for (int t = 0; t < 8; t++) {
        int alive = __syncthreads_or((tid < 32) ? (sCarry[tid] != 0.f) : 0);
        if (!alive) break;

        // A1: s = sigmoid(decay at reversed index), chunk products
        float p = 1.f;
        #pragma unroll
        for (int jj = 0; jj < 16; jj++) {
            int j = c * 16 + jj;
            int n = t * 128 + j;
            float s;
            if (n == 0) {
                s = 1.f;
            } else {
                int m = 1024 - n;
                s = sigmoidf_(dk[m * 32 + d] * dh[m]);
            }
            p *= s;
            sK[j][d] = s;  // stash sigmoid
        }
        sProd[c][d] = p;
        __syncthreads();

        // A2 + B: per-chunk prefix product, build K = silu(k0*kh)*w, V = silu(v0*vh)
        float p2 = sCarry[d];
        for (int cc = 0; cc < c; cc++) p2 *= sProd[cc][d];
        #pragma unroll
        for (int jj = 0; jj < 16; jj++) {
            int j = c * 16 + jj;
            int n = t * 128 + j;
            p2 *= sK[j][d];
            float kr = k0[n * 32 + d] * kh[n];
            float vr = v0[n * 32 + d] * vh[n];
            sK[j][d] = siluf_(kr) * p2;
            sV[j][d] = siluf_(vr);
        }
        if (c == 7) sCarry[d] = p2;
        __syncthreads();

        // C: rank-128 update of the 32x32 accumulator, split 4-way over j
        #pragma unroll 4
        for (int jj = 0; jj < 32; jj++) {
            int j = jq * 32 + jj;
            float4 kv = *reinterpret_cast<const float4*>(&sK[j][dg * 4]);
            float4 vv = *reinterpret_cast<const float4*>(&sV[j][eg * 4]);
            float kvx[4] = {kv.x, kv.y, kv.z, kv.w};
            float vvx[4] = {vv.x, vv.y, vv.z, vv.w};
            #pragma unroll
            for (int i = 0; i < 4; i++)
                #pragma unroll
                for (int q = 0; q < 4; q++)
                    acc[i][q] = fmaf(kvx[i], vvx[q], acc[i][q]);
        }
        __syncthreads();
    }

    // Reduce the 4 jq-partials through smem (reuse sK as 4096-float scratch)
    float* red = &sK[0][0];
    #pragma unroll
    for (int i = 0; i < 4; i++)
        #pragma unroll
        for (int q = 0; q < 4; q++)
            red[jq * 1024 + (dg * 4 + i) * 32 + eg * 4 + q] = acc[i][q];
    __syncthreads();

    float4 r0 = *reinterpret_cast<const float4*>(&red[tid * 4]);
    float4 r1 = *reinterpret_cast<const float4*>(&red[1024 + tid * 4]);
    float4 r2 = *reinterpret_cast<const float4*>(&red[2048 + tid * 4]);
    float4 r3 = *reinterpret_cast<const float4*>(&red[3072 + tid * 4]);
    float o0 = (r0.x + r1.x) + (r2.x + r3.x);
    float o1 = (r0.y + r1.y) + (r2.y + r3.y);
    float o2 = (r0.z + r1.z) + (r2.z + r3.z);
    float o3 = (r0.w + r1.w) + (r2.w + r3.w);

    float* op = out + (size_t)b * OUT_PER_B + (size_t)(tid * 4) * 256 + h;
    op[0]   = o0;
    op[256] = o1;
    op[512] = o2;
    op[768] = o3;
}

extern "C" void kernel_launch(void* const* d_in, const int* in_sizes, int n_in,
                              void* d_out, int out_size) {
    (void)in_sizes; (void)n_in; (void)out_size;
    const float* token = (const float*)d_in[0];
    const float* Wkv   = (const float*)d_in[1];
    const float* Wkvh  = (const float*)d_in[2];
    const float* Wd    = (const float*)d_in[3];
    const float* Wdh   = (const float*)d_in[4];

    proj_kernel<<<dim3(27, 64), 256>>>(token, Wkv, Wkvh, Wd, Wdh);
    accum_kernel<<<dim3(B_ * H_), 256>>>((float*)d_out);
}

// round 2
// speedup vs baseline: 1.2540x; 1.2540x over previous
#include <cuda_runtime.h>

// Problem constants
#define B_ 4
#define N_ 1024
#define H_ 256
#define D_ 32
#define M_ (B_ * N_)              // 4096 token rows
#define OUT_PER_B (D_ * D_ * H_)  // 262144

// Scratch (device globals — no allocation allowed)
__device__ float g_k0[M_ * D_];        // [b][n][d]
__device__ float g_v0[M_ * D_];        // [b][n][d]
__device__ float g_dk[M_ * D_];        // [b][n][d]
__device__ float g_khT[B_ * H_ * N_];  // [b][h][n]
__device__ float g_vhT[B_ * H_ * N_];  // [b][h][n]
__device__ float g_dhT[B_ * H_ * N_];  // [b][h][n]

// ---- packed f32x2 helpers (sm_103a FFMA2 path) ----
typedef unsigned long long ull;
__device__ __forceinline__ ull pack2(float lo, float hi) {
    ull r; asm("mov.b64 %0, {%1, %2};" : "=l"(r) : "f"(lo), "f"(hi)); return r;
}
__device__ __forceinline__ void unpack2(float& lo, float& hi, ull v) {
    asm("mov.b64 {%0, %1}, %2;" : "=f"(lo), "=f"(hi) : "l"(v));
}
__device__ __forceinline__ void fma2(ull& d, ull a, ull b) {
    asm("fma.rn.f32x2 %0, %1, %2, %3;" : "=l"(d) : "l"(a), "l"(b), "l"(d));
}

// ---- fast activations: 1 MUFU each via tanh.approx ----
__device__ __forceinline__ float tanhfast(float x) {
    float y; asm("tanh.approx.f32 %0, %1;" : "=f"(y) : "f"(x)); return y;
}
__device__ __forceinline__ float sigf(float x) {          // sigmoid
    return fmaf(tanhfast(0.5f * x), 0.5f, 0.5f);
}
__device__ __forceinline__ float siluf(float x) {         // x*sigmoid(x)
    float h = 0.5f * x;
    return fmaf(h, tanhfast(h), h);
}

__device__ __forceinline__ void route32(int cbase,
    const float* Wkv, const float* Wkvh, const float* Wd, const float* Wdh,
    const float*& Wp, int& width, int& coff)
{
    if (cbase < 64)       { Wp = Wkv;  width = 64;  coff = cbase;       }
    else if (cbase < 576) { Wp = Wkvh; width = 512; coff = cbase - 64;  }
    else if (cbase < 608) { Wp = Wd;   width = 32;  coff = cbase - 576; }
    else                  { Wp = Wdh;  width = 256; coff = cbase - 608; }
}

// ---------------------------------------------------------------------------
// Pass 1: projection GEMM with FFMA2. Tile 128m x 64n, 128 threads,
// microtile 8x8 (1 B of LDS per FMA -> crossbar-balanced at 128 FMA/cyc/SM).
// 864 cols handled as 14 tiles of 64; last tile's upper half is clamped
// (computed but not stored).
// ---------------------------------------------------------------------------
__global__ __launch_bounds__(128) void proj_kernel(
    const float* __restrict__ token,
    const float* __restrict__ Wkv,
    const float* __restrict__ Wkvh,
    const float* __restrict__ Wd,
    const float* __restrict__ Wdh)
{
    __shared__ __align__(16) float As[128][33];  // [m][k], stride 33: STS + broadcast-read conflict-free
    __shared__ __align__(16) float Bs[32][68];   // [k][c]

    const int tid = threadIdx.x;
    const int tn = tid & 7;    // n-group: cols tn*8..+8
    const int tm = tid >> 3;   // m-group: rows tm*8..+8 (0..15)
    const int m0 = blockIdx.y * 128;
    const int n0 = blockIdx.x * 64;

    const float* Wp[2]; int wwid[2], wcoff[2];
    #pragma unroll
    for (int hh = 0; hh < 2; hh++) {
        int ch = n0 + hh * 32;
        if (ch >= 864) ch = 832;  // clamp: duplicate data, stores guarded
        route32(ch, Wkv, Wkvh, Wd, Wdh, Wp[hh], wwid[hh], wcoff[hh]);
    }

    ull acc[8][4];
    #pragma unroll
    for (int i = 0; i < 8; i++)
        #pragma unroll
        for (int p = 0; p < 4; p++) acc[i][p] = 0ull;

    for (int kt = 0; kt < 256; kt += 32) {
        // A tile: 128 rows x 32 k (row-major, coalesced LDG.128)
        #pragma unroll
        for (int p = 0; p < 8; p++) {
            int row = p * 16 + tm;
            float4 a = *reinterpret_cast<const float4*>(
                &token[(size_t)(m0 + row) * 256 + kt + tn * 4]);
            As[row][tn * 4 + 0] = a.x;
            As[row][tn * 4 + 1] = a.y;
            As[row][tn * 4 + 2] = a.z;
            As[row][tn * 4 + 3] = a.w;
        }
        // B tile: 32 k x 64 c, two 32-col halves with own source
        #pragma unroll
        for (int hh = 0; hh < 2; hh++) {
            #pragma unroll
            for (int p = 0; p < 2; p++) {
                int k = p * 16 + tm;
                float4 bv = *reinterpret_cast<const float4*>(
                    &Wp[hh][(size_t)(kt + k) * wwid[hh] + wcoff[hh] + tn * 4]);
                *reinterpret_cast<float4*>(&Bs[k][hh * 32 + tn * 4]) = bv;
            }
        }
        __syncthreads();

        #pragma unroll 4
        for (int kk = 0; kk < 32; kk++) {
            float4 b0 = *reinterpret_cast<const float4*>(&Bs[kk][tn * 8]);
            float4 b1 = *reinterpret_cast<const float4*>(&Bs[kk][tn * 8 + 4]);
            ull bp0 = pack2(b0.x, b0.y);
            ull bp1 = pack2(b0.z, b0.w);
            ull bp2 = pack2(b1.x, b1.y);
            ull bp3 = pack2(b1.z, b1.w);
            #pragma unroll
            for (int i = 0; i < 8; i++) {
                float av = As[tm * 8 + i][kk];
                ull ad = pack2(av, av);
                fma2(acc[i][0], ad, bp0);
                fma2(acc[i][1], ad, bp1);
                fma2(acc[i][2], ad, bp2);
                fma2(acc[i][3], ad, bp3);
            }
        }
        __syncthreads();
    }

    // Epilogue: route this thread's 8-col group (always within one region:
    // boundaries 32/64/320/576/608 are all multiples of 8 >= group width)
    const int cg0 = n0 + tn * 8;
    if (cg0 >= 864) return;

    float* dptr = nullptr; int dd0 = 0;
    float* hptr = nullptr; int hb = 0;
    if (cg0 < 32)       { dptr = g_k0;  dd0 = cg0; }
    else if (cg0 < 64)  { dptr = g_v0;  dd0 = cg0 - 32; }
    else if (cg0 < 320) { hptr = g_khT; hb  = cg0 - 64; }
    else if (cg0 < 576) { hptr = g_vhT; hb  = cg0 - 320; }
    else if (cg0 < 608) { dptr = g_dk;  dd0 = cg0 - 576; }
    else                { hptr = g_dhT; hb  = cg0 - 608; }

    const int b = m0 >> 10;  // m-tile (128) never straddles a batch (1024)

    #pragma unroll
    for (int i = 0; i < 8; i++) {
        int m = m0 + tm * 8 + i;
        float r[8];
        unpack2(r[0], r[1], acc[i][0]);
        unpack2(r[2], r[3], acc[i][1]);
        unpack2(r[4], r[5], acc[i][2]);
        unpack2(r[6], r[7], acc[i][3]);
        if (dptr) {
            float4 v0 = make_float4(r[0], r[1], r[2], r[3]);
            float4 v1 = make_float4(r[4], r[5], r[6], r[7]);
            *reinterpret_cast<float4*>(&dptr[m * 32 + dd0])     = v0;
            *reinterpret_cast<float4*>(&dptr[m * 32 + dd0 + 4]) = v1;
        } else {
            int n = m & 1023;
            #pragma unroll
            for (int q = 0; q < 8; q++)
                hptr[(size_t)((b << 8) + hb + q) * 1024 + n] = r[q];
        }
    }
}

// ---------------------------------------------------------------------------
// Pass 2: per (b,h) — reversed sigmoid running-product weights (tanh-based),
// silu gating, FFMA2 rank-128 updates of the 32x32 accumulator with a 16-way
// j-split (8x8 microtiles, 1 B/FMA). Early-exits when all 32 per-d carries
// underflow to exact fp32 zero (matches reference exp(-huge)=0).
// ---------------------------------------------------------------------------
#define KST 36  // smem row stride for K/V tiles

__global__ __launch_bounds__(256) void accum_kernel(float* __restrict__ out)
{
    __shared__ __align__(16) float smem_buf[128 * KST * 2 + 8 * 32 + 32];
    float (*sK)[KST] = reinterpret_cast<float(*)[KST]>(smem_buf);
    float (*sV)[KST] = reinterpret_cast<float(*)[KST]>(smem_buf + 128 * KST);
    float* sProd  = smem_buf + 128 * KST * 2;   // [8][32]
    float* sCarry = sProd + 8 * 32;             // [32]

    const int tid = threadIdx.x;
    const int bh = blockIdx.x;
    const int b = bh >> 8;
    const int h = bh & 255;

    const float* __restrict__ dk = g_dk + b * N_ * D_;
    const float* __restrict__ k0 = g_k0 + b * N_ * D_;
    const float* __restrict__ v0 = g_v0 + b * N_ * D_;
    const float* __restrict__ dh = g_dhT + ((size_t)b * H_ + h) * N_;
    const float* __restrict__ kh = g_khT + ((size_t)b * H_ + h) * N_;
    const float* __restrict__ vh = g_vhT + ((size_t)b * H_ + h) * N_;

    if (tid < 32) sCarry[tid] = 1.f;

    // phase A/B mapping: chunk c owns tile-local j in [16c,16c+16), lane d
    const int c = tid >> 5, d = tid & 31;
    // phase C mapping: j-slice js (j = jj*16+js), 4x4 thread grid of 8x8 tiles
    const int js = tid >> 4;          // 0..15
    const int td = (tid >> 2) & 3;    // d base td*8
    const int te = tid & 3;           // e base te*8

    ull acc[8][4];
    #pragma unroll
    for (int i = 0; i < 8; i++)
        #pragma unroll
        for (int p = 0; p < 4; p++) acc[i][p] = 0ull;

    for (int t = 0; t < 8; t++) {
        int alive = __syncthreads_or((tid < 32) ? (sCarry[tid] != 0.f) : 0);
        if (!alive) break;

        // A1: sigmoids at reversed index, kept in registers; chunk product
        float sreg[16];
        float p = 1.f;
        #pragma unroll
        for (int jj = 0; jj < 16; jj++) {
            int n = t * 128 + c * 16 + jj;
            float s;
            if (n == 0) s = 1.f;
            else {
                int mm = 1024 - n;
                s = sigf(dk[mm * 32 + d] * dh[mm]);
            }
            sreg[jj] = s;
            p *= s;
        }
        sProd[c * 32 + d] = p;
        __syncthreads();

        // A2+B: prefix product across chunks, build K/V tiles
        float p2 = sCarry[d];
        #pragma unroll
        for (int cc = 0; cc < 7; cc++)
            if (cc < c) p2 *= sProd[cc * 32 + d];
        #pragma unroll
        for (int jj = 0; jj < 16; jj++) {
            int j = c * 16 + jj;
            int n = t * 128 + j;
            p2 *= sreg[jj];
            float kr = k0[n * 32 + d] * kh[n];
            float vr = v0[n * 32 + d] * vh[n];
            sK[j][d] = siluf(kr) * p2;
            sV[j][d] = siluf(vr);
        }
        if (c == 7) sCarry[d] = p2;
        __syncthreads();

        // C: rank-128 FFMA2 update, 16-way j-split, conflict-free LDS
        #pragma unroll
        for (int jj = 0; jj < 8; jj++) {
            int j = jj * 16 + js;
            float4 ka0 = *reinterpret_cast<const float4*>(&sK[j][td * 8]);
            float4 ka1 = *reinterpret_cast<const float4*>(&sK[j][td * 8 + 4]);
            float4 va0 = *reinterpret_cast<const float4*>(&sV[j][te * 8]);
            float4 va1 = *reinterpret_cast<const float4*>(&sV[j][te * 8 + 4]);
            ull vb0 = pack2(va0.x, va0.y);
            ull vb1 = pack2(va0.z, va0.w);
            ull vb2 = pack2(va1.x, va1.y);
            ull vb3 = pack2(va1.z, va1.w);
            float k8[8] = {ka0.x, ka0.y, ka0.z, ka0.w, ka1.x, ka1.y, ka1.z, ka1.w};
            #pragma unroll
            for (int i = 0; i < 8; i++) {
                ull kd = pack2(k8[i], k8[i]);
                fma2(acc[i][0], kd, vb0);
                fma2(acc[i][1], kd, vb1);
                fma2(acc[i][2], kd, vb2);
                fma2(acc[i][3], kd, vb3);
            }
        }
        __syncthreads();
    }

    // Reduce 16 j-slice partials (overlay scratch on sK/sV region)
    float* red = smem_buf;  // needs 8*1024 floats <= 128*KST*2
    __syncthreads();

    float af[8][8];
    #pragma unroll
    for (int i = 0; i < 8; i++) {
        unpack2(af[i][0], af[i][1], acc[i][0]);
        unpack2(af[i][2], af[i][3], acc[i][1]);
        unpack2(af[i][4], af[i][5], acc[i][2]);
        unpack2(af[i][6], af[i][7], acc[i][3]);
    }

    if (js < 8) {
        #pragma unroll
        for (int i = 0; i < 8; i++) {
            int off = js * 1024 + (td * 8 + i) * 32 + te * 8;
            *reinterpret_cast<float4*>(&red[off])     = make_float4(af[i][0], af[i][1], af[i][2], af[i][3]);
            *reinterpret_cast<float4*>(&red[off + 4]) = make_float4(af[i][4], af[i][5], af[i][6], af[i][7]);
        }
    }
    __syncthreads();
    if (js >= 8) {
        #pragma unroll
        for (int i = 0; i < 8; i++) {
            int off = (js - 8) * 1024 + (td * 8 + i) * 32 + te * 8;
            float4 r0 = *reinterpret_cast<const float4*>(&red[off]);
            float4 r1 = *reinterpret_cast<const float4*>(&red[off + 4]);
            r0.x += af[i][0]; r0.y += af[i][1]; r0.z += af[i][2]; r0.w += af[i][3];
            r1.x += af[i][4]; r1.y += af[i][5]; r1.z += af[i][6]; r1.w += af[i][7];
            *reinterpret_cast<float4*>(&red[off])     = r0;
            *reinterpret_cast<float4*>(&red[off + 4]) = r1;
        }
    }
    __syncthreads();

    // Final: each thread sums 8 partials for 4 consecutive de-indices
    float4 s = make_float4(0.f, 0.f, 0.f, 0.f);
    #pragma unroll
    for (int pp = 0; pp < 8; pp++) {
        float4 r = *reinterpret_cast<const float4*>(&red[pp * 1024 + tid * 4]);
        s.x += r.x; s.y += r.y; s.z += r.z; s.w += r.w;
    }
    float* op = out + (size_t)b * OUT_PER_B + (size_t)(tid * 4) * 256 + h;
    op[0]   = s.x;
    op[256] = s.y;
    op[512] = s.z;
    op[768] = s.w;
}

extern "C" void kernel_launch(void* const* d_in, const int* in_sizes, int n_in,
                              void* d_out, int out_size) {
    (void)in_sizes; (void)n_in; (void)out_size;
    const float* token = (const float*)d_in[0];
    const float* Wkv   = (const float*)d_in[1];
    const float* Wkvh  = (const float*)d_in[2];
    const float* Wd    = (const float*)d_in[3];
    const float* Wdh   = (const float*)d_in[4];

    proj_kernel<<<dim3(14, 32), 128>>>(token, Wkv, Wkvh, Wd, Wdh);
    accum_kernel<<<dim3(B_ * H_), 256>>>((float*)d_out);
}